// round 1
// baseline (speedup 1.0000x reference)
#include <cuda_runtime.h>
#include <math.h>

#define Bn   16
#define Tn   256
#define Un   64
#define UP1  65
#define V1   513
#define BLANK_IDX 512

// Scratch (allocation-free rule: __device__ globals)
__device__ float g_blank[Bn * Tn * UP1];   // blank_lp[b][t][u]
__device__ float g_lab  [Bn * Tn * Un];    // lab_lp[b][t][u]
__device__ float g_loss [Bn];

// ---------------------------------------------------------------------------
// Kernel 1: per-(b,t,u) row logsumexp over V1=513 logits (single pass, online),
// extract blank & label logits in the same pass. One warp per row.
// ---------------------------------------------------------------------------
__global__ void lse_kernel(const float* __restrict__ logits,
                           const int*   __restrict__ y)
{
    int warp = (blockIdx.x * blockDim.x + threadIdx.x) >> 5;
    int lane = threadIdx.x & 31;
    if (warp >= Bn * Tn * UP1) return;

    int b   = warp / (Tn * UP1);
    int rem = warp % (Tn * UP1);
    int t   = rem / UP1;
    int u   = rem % UP1;

    int yv = (u < Un) ? y[b * Un + u] : -1;   // label index (never == BLANK)

    const float* row = logits + (size_t)warp * V1;

    float m = -INFINITY, s = 0.f;
    float blankv = -INFINITY, labv = -INFINITY;

    #pragma unroll 4
    for (int j = lane; j < V1; j += 32) {
        float x = __ldcs(row + j);           // streaming: don't pollute L2
        if (j == BLANK_IDX) blankv = x;
        if (j == yv)        labv   = x;
        if (x > m) { s = s * __expf(m - x) + 1.f; m = x; }
        else       { s += __expf(x - m); }
    }

    // warp-reduce (m,s) pairs + max-reduce the captured logits
    #pragma unroll
    for (int o = 16; o; o >>= 1) {
        float m2 = __shfl_xor_sync(0xFFFFFFFFu, m, o);
        float s2 = __shfl_xor_sync(0xFFFFFFFFu, s, o);
        if (m2 > m) { s = s * __expf(m - m2) + s2; m = m2; }
        else        { s += s2 * __expf(m2 - m); }
        blankv = fmaxf(blankv, __shfl_xor_sync(0xFFFFFFFFu, blankv, o));
        labv   = fmaxf(labv,   __shfl_xor_sync(0xFFFFFFFFu, labv,   o));
    }

    if (lane == 0) {
        float lse = m + logf(s);
        g_blank[warp] = blankv - lse;        // warp == b*Tn*UP1 + t*UP1 + u
        if (u < Un)
            g_lab[(b * Tn + t) * Un + u] = labv - lse;
    }
}

// ---------------------------------------------------------------------------
// Kernel 2: alpha wavefront DP per batch element. Stage blank/lab into SMEM,
// sweep 320 anti-diagonals with one barrier each.
// alpha[t,u] = logaddexp(alpha[t-1,u] + blank[t-1,u], alpha[t,u-1] + lab[t,u-1])
// ---------------------------------------------------------------------------
__global__ void alpha_kernel(const int* __restrict__ logit_lens,
                             const int* __restrict__ y_lens)
{
    extern __shared__ float sm[];
    float* sb = sm;                   // [Tn*UP1] blank_lp
    float* sl = sb + Tn * UP1;        // [Tn*Un]  lab_lp
    float* dA = sl + Tn * Un;         // diag buffer A [UP1]
    float* dB = dA + UP1;             // diag buffer B [UP1]

    const int b   = blockIdx.x;
    const int tid = threadIdx.x;

    for (int i = tid; i < Tn * UP1; i += blockDim.x)
        sb[i] = g_blank[b * Tn * UP1 + i];
    for (int i = tid; i < Tn * Un; i += blockDim.x)
        sl[i] = g_lab[b * Tn * Un + i];
    __syncthreads();

    const int Tl = logit_lens[b];     // in [128, 256]
    const int Ul = y_lens[b];         // in [32, 64]
    const int u  = tid;

    float* prev = dA;
    float* cur  = dB;

    if (u == 0) cur[0] = 0.f;         // alpha[0,0] = 0
    __syncthreads();

    for (int d = 1; d <= (Tn - 1) + Un; ++d) {
        float* tmp = prev; prev = cur; cur = tmp;
        if (u <= Un) {
            int t = d - u;
            if (t >= 0 && t < Tn) {
                float va = (t >= 1) ? prev[u]     + sb[(t - 1) * UP1 + u]   : -INFINITY;
                float vb = (u >= 1) ? prev[u - 1] + sl[t * Un + (u - 1)]    : -INFINITY;
                float mx = fmaxf(va, vb), mn = fminf(va, vb);
                float a  = (mn == -INFINITY) ? mx : mx + log1pf(__expf(mn - mx));
                cur[u] = a;
                if (t == Tl - 1 && u == Ul)
                    g_loss[b] = -(a + sb[t * UP1 + u]);
            }
        }
        __syncthreads();
    }
}

// ---------------------------------------------------------------------------
// Kernel 3: mean over batch
// ---------------------------------------------------------------------------
__global__ void reduce_kernel(float* __restrict__ out)
{
    float v = (threadIdx.x < Bn) ? g_loss[threadIdx.x] : 0.f;
    #pragma unroll
    for (int o = 16; o; o >>= 1)
        v += __shfl_xor_sync(0xFFFFFFFFu, v, o);
    if (threadIdx.x == 0) out[0] = v * (1.0f / Bn);
}

// ---------------------------------------------------------------------------
extern "C" void kernel_launch(void* const* d_in, const int* in_sizes, int n_in,
                              void* d_out, int out_size)
{
    const float* logits     = (const float*)d_in[0];
    const int*   logit_lens = (const int*)  d_in[1];
    const int*   y          = (const int*)  d_in[2];
    const int*   y_lens     = (const int*)  d_in[3];

    (void)in_sizes; (void)n_in; (void)out_size;

    // Kernel 1: one warp per row, 256 threads/block (8 warps)
    const int totalWarps = Bn * Tn * UP1;            // 266240
    const int blocks     = (totalWarps + 7) / 8;     // 33280
    lse_kernel<<<blocks, 256>>>(logits, y);

    // Kernel 2: one block per batch, big dynamic smem
    const int SMEM_BYTES = (Tn * UP1 + Tn * Un + 2 * UP1) * (int)sizeof(float); // 132616
    cudaFuncSetAttribute(alpha_kernel,
                         cudaFuncAttributeMaxDynamicSharedMemorySize, SMEM_BYTES);
    alpha_kernel<<<Bn, 128, SMEM_BYTES>>>(logit_lens, y_lens);

    // Kernel 3: mean
    reduce_kernel<<<1, 32>>>((float*)d_out);
}

// round 2
// speedup vs baseline: 1.4757x; 1.4757x over previous
#include <cuda_runtime.h>
#include <math.h>

#define Bn   16
#define Tn   256
#define Un   64
#define UP1  65
#define V1   513
#define BLANK_IDX 512
#define NROWS (Bn * Tn * UP1)

// Scratch (__device__ globals per allocation-free rule), TRANSPOSED [b][u][t]
// so the alpha wavefront's diagonal shared-memory accesses are conflict-free.
__device__ float g_blankT[Bn * UP1 * Tn];
__device__ float g_labT  [Bn * Un  * Tn];
__device__ float g_loss  [Bn];

// ---------------------------------------------------------------------------
// Kernel 1: one warp per (b,t,u) row of 513 logits. Two-pass logsumexp with
// the row buffered in registers (17 per lane): pass 1 = 17 LDG + fmax chain,
// pass 2 = fma + MUFU.EX2 + fadd per element. No branches in the hot loop.
// Warp index is remapped so t is fastest -> lane-0 stores to the transposed
// outputs are consecutive across adjacent warps (sector-coalesced in L2).
// ---------------------------------------------------------------------------
__global__ __launch_bounds__(256) void lse_kernel(const float* __restrict__ logits,
                                                  const int*   __restrict__ y)
{
    const int w    = (blockIdx.x * blockDim.x + threadIdx.x) >> 5;
    const int lane = threadIdx.x & 31;
    if (w >= NROWS) return;

    const int t  = w % Tn;
    const int bu = w / Tn;
    const int u  = bu % UP1;
    const int b  = bu / UP1;

    const float* row = logits + (size_t)((b * Tn + t) * UP1 + u) * V1;

    // pass 0: load 513 elements, 17 per lane (j = lane + 32k), MLP=17
    float v[17];
    #pragma unroll
    for (int k = 0; k < 16; ++k)
        v[k] = __ldcs(row + lane + 32 * k);
    v[16] = (lane == 0) ? __ldcs(row + BLANK_IDX) : -INFINITY;  // j=512 only on lane 0

    // pass 1: max
    float m = v[0];
    #pragma unroll
    for (int k = 1; k < 17; ++k) m = fmaxf(m, v[k]);
    #pragma unroll
    for (int o = 16; o; o >>= 1) m = fmaxf(m, __shfl_xor_sync(0xFFFFFFFFu, m, o));

    // pass 2: sum exp2(v*log2e - m*log2e)  (3 instr/element: FFMA, MUFU, FADD)
    const float LOG2E = 1.4426950408889634f;
    const float m2 = m * LOG2E;
    float s = 0.f;
    #pragma unroll
    for (int k = 0; k < 17; ++k)
        s += exp2f(__fmaf_rn(v[k], LOG2E, -m2));
    #pragma unroll
    for (int o = 16; o; o >>= 1) s += __shfl_xor_sync(0xFFFFFFFFu, s, o);

    if (lane == 0) {
        const float lse = m + __logf(s);
        g_blankT[(b * UP1 + u) * Tn + t] = v[16] - lse;     // blank logit = v[16]
        if (u < Un) {
            const int yv = y[b * Un + u];
            g_labT[(b * Un + u) * Tn + t] = __ldg(row + yv) - lse;
        }
    }
}

// ---------------------------------------------------------------------------
// logaddexp in log space (fast intrinsics; guarded for the (-inf,-inf) case)
// ---------------------------------------------------------------------------
__device__ __forceinline__ float laep(float x, float y)
{
    float mx = fmaxf(x, y);
    float mn = fminf(x, y);
    float r  = mx + __logf(1.f + __expf(mn - mx));
    return (mx > -INFINITY) ? r : -INFINITY;
}

// ---------------------------------------------------------------------------
// Kernel 2: alpha wavefront, one block per batch. 256 threads stage the
// transposed blank/lab arrays (contiguous, coalesced) into dynamic SMEM; then
// warp 0 alone sweeps 320 anti-diagonals with state in registers:
//   lane l holds alpha at u=l (a0) and u=32+l (a1); lane 0 also u=64 (a2).
// u-1 dependency travels via shfl_up -- zero barriers, conflict-free LDS
// (transposed layout: lane stride = 255 words == 31 mod 32 banks).
// ---------------------------------------------------------------------------
__global__ __launch_bounds__(256) void alpha_kernel(const int* __restrict__ logit_lens,
                                                    const int* __restrict__ y_lens)
{
    extern __shared__ float sm[];
    float* sb = sm;                 // [UP1][Tn]
    float* sl = sm + UP1 * Tn;      // [Un][Tn]

    const int b   = blockIdx.x;
    const int tid = threadIdx.x;

    const float* gb = g_blankT + b * UP1 * Tn;
    const float* gl = g_labT   + b * Un  * Tn;
    for (int i = tid; i < UP1 * Tn; i += blockDim.x) sb[i] = gb[i];
    for (int i = tid; i < Un  * Tn; i += blockDim.x) sl[i] = gl[i];
    __syncthreads();

    if (tid >= 32) return;          // warp 0 only from here; no more barriers
    const int lane = tid;
    const int Tl = logit_lens[b];
    const int Ul = y_lens[b];

    const int u0 = lane;
    const int u1 = 32 + lane;

    float a0 = (lane == 0) ? 0.f : -INFINITY;   // alpha[0,0] = 0 (diag 0)
    float a1 = -INFINITY;
    float a2 = -INFINITY;                       // u = 64 (lane 0 only)

    float myloss = 0.f;
    int   hit    = 0;

    #pragma unroll 4
    for (int d = 1; d <= (Tn - 1) + Un; ++d) {
        float p0    = __shfl_up_sync(0xFFFFFFFFu, a0, 1);   // prev alpha[u-1] for u0
        float p1    = __shfl_up_sync(0xFFFFFFFFu, a1, 1);   // prev alpha[u-1] for u1
        float a0_31 = __shfl_sync   (0xFFFFFFFFu, a0, 31);  // prev alpha[31]
        float a1_31 = __shfl_sync   (0xFFFFFFFFu, a1, 31);  // prev alpha[63]
        if (lane == 0) p1 = a0_31;

        float n0 = -INFINITY, n1 = -INFINITY, n2 = -INFINITY;

        {   // u = u0 (0..31)
            int t = d - u0;
            if (t >= 0 && t < Tn) {
                float va = (t  >= 1) ? a0 + sb[u0 * Tn + (t - 1)]       : -INFINITY;
                float vb = (u0 >= 1) ? p0 + sl[(u0 - 1) * Tn + t]       : -INFINITY;
                n0 = laep(va, vb);
                if (t == Tl - 1 && u0 == Ul) { myloss = -(n0 + sb[u0 * Tn + t]); hit = 1; }
            }
        }
        {   // u = u1 (32..63), u-1 always valid
            int t = d - u1;
            if (t >= 0 && t < Tn) {
                float va = (t >= 1) ? a1 + sb[u1 * Tn + (t - 1)] : -INFINITY;
                float vb = p1 + sl[(u1 - 1) * Tn + t];
                n1 = laep(va, vb);
                if (t == Tl - 1 && u1 == Ul) { myloss = -(n1 + sb[u1 * Tn + t]); hit = 1; }
            }
        }
        if (lane == 0) {  // u = 64
            int t = d - 64;
            if (t >= 0 && t < Tn) {
                float va = (t >= 1) ? a2 + sb[64 * Tn + (t - 1)] : -INFINITY;
                float vb = a1_31 + sl[63 * Tn + t];
                n2 = laep(va, vb);
                if (t == Tl - 1 && 64 == Ul) { myloss = -(n2 + sb[64 * Tn + t]); hit = 1; }
            }
        }
        a0 = n0; a1 = n1; a2 = n2;
    }

    if (hit) g_loss[b] = myloss;
}

// ---------------------------------------------------------------------------
// Kernel 3: mean over batch
// ---------------------------------------------------------------------------
__global__ void reduce_kernel(float* __restrict__ out)
{
    float v = (threadIdx.x < Bn) ? g_loss[threadIdx.x] : 0.f;
    #pragma unroll
    for (int o = 16; o; o >>= 1)
        v += __shfl_xor_sync(0xFFFFFFFFu, v, o);
    if (threadIdx.x == 0) out[0] = v * (1.0f / Bn);
}

// ---------------------------------------------------------------------------
extern "C" void kernel_launch(void* const* d_in, const int* in_sizes, int n_in,
                              void* d_out, int out_size)
{
    const float* logits     = (const float*)d_in[0];
    const int*   logit_lens = (const int*)  d_in[1];
    const int*   y          = (const int*)  d_in[2];
    const int*   y_lens     = (const int*)  d_in[3];
    (void)in_sizes; (void)n_in; (void)out_size;

    const int blocks = (NROWS + 7) / 8;          // 8 warps / 256 threads per block
    lse_kernel<<<blocks, 256>>>(logits, y);

    const int SMEM_BYTES = (UP1 * Tn + Un * Tn) * (int)sizeof(float);  // 132096
    cudaFuncSetAttribute(alpha_kernel,
                         cudaFuncAttributeMaxDynamicSharedMemorySize, SMEM_BYTES);
    alpha_kernel<<<Bn, 256, SMEM_BYTES>>>(logit_lens, y_lens);

    reduce_kernel<<<1, 32>>>((float*)d_out);
}

// round 3
// speedup vs baseline: 2.0778x; 1.4080x over previous
#include <cuda_runtime.h>
#include <math.h>

#define Bn   16
#define Tn   256
#define Un   64
#define UP1  65
#define V1   513
#define BLANK_IDX 512
#define NROWS (Bn * Tn * UP1)

// Scratch (__device__ globals per allocation-free rule), TRANSPOSED [b][u][t]
__device__ float g_blankT[Bn * UP1 * Tn];
__device__ float g_labT  [Bn * Un  * Tn];
__device__ float g_loss  [Bn];

// ---------------------------------------------------------------------------
// Kernel 1: one warp per (b,t,u) row of 513 logits. Two-pass logsumexp with
// the row buffered in 17 registers. Near HBM roofline (75% DRAM) — unchanged.
// ---------------------------------------------------------------------------
__global__ __launch_bounds__(256) void lse_kernel(const float* __restrict__ logits,
                                                  const int*   __restrict__ y)
{
    const int w    = (blockIdx.x * blockDim.x + threadIdx.x) >> 5;
    const int lane = threadIdx.x & 31;
    if (w >= NROWS) return;

    const int t  = w % Tn;
    const int bu = w / Tn;
    const int u  = bu % UP1;
    const int b  = bu / UP1;

    const float* row = logits + (size_t)((b * Tn + t) * UP1 + u) * V1;

    float v[17];
    #pragma unroll
    for (int k = 0; k < 16; ++k)
        v[k] = __ldcs(row + lane + 32 * k);
    v[16] = (lane == 0) ? __ldcs(row + BLANK_IDX) : -INFINITY;

    float m = v[0];
    #pragma unroll
    for (int k = 1; k < 17; ++k) m = fmaxf(m, v[k]);
    #pragma unroll
    for (int o = 16; o; o >>= 1) m = fmaxf(m, __shfl_xor_sync(0xFFFFFFFFu, m, o));

    const float LOG2E = 1.4426950408889634f;
    const float m2 = m * LOG2E;
    float s = 0.f;
    #pragma unroll
    for (int k = 0; k < 17; ++k)
        s += exp2f(__fmaf_rn(v[k], LOG2E, -m2));
    #pragma unroll
    for (int o = 16; o; o >>= 1) s += __shfl_xor_sync(0xFFFFFFFFu, s, o);

    if (lane == 0) {
        const float lse = m + __logf(s);
        g_blankT[(b * UP1 + u) * Tn + t] = v[16] - lse;
        if (u < Un) {
            const int yv = y[b * Un + u];
            g_labT[(b * Un + u) * Tn + t] = __ldg(row + yv) - lse;
        }
    }
}

// logaddexp: NaN from (-inf,-inf) is cleaned by the final select.
__device__ __forceinline__ float laep2(float x, float y)
{
    float mx = fmaxf(x, y);
    float mn = fminf(x, y);
    float r  = mx + __logf(1.f + __expf(mn - mx));
    return (mx == -INFINITY) ? -INFINITY : r;
}

// ---------------------------------------------------------------------------
// Kernel 2: alpha wavefront, one block per batch; warp 0 sweeps 320 diagonals.
// Lane l holds alpha at u=l (a0), u=32+l (a1); a2 mirrors u=64 (lane 0 valid).
// Fully uniform loop: validity propagates through -INF arithmetic (no guards);
// all smem offsets are (per-lane const + d); 2 rotating shfls per diagonal.
// Out-of-band cells compute finite garbage that provably never feeds a valid
// cell (a valid (t,u) only reads (t-1,u) and (t,u-1), both valid).
// ---------------------------------------------------------------------------
__global__ __launch_bounds__(256) void alpha_kernel(const int* __restrict__ logit_lens,
                                                    const int* __restrict__ y_lens)
{
    extern __shared__ float sm[];
    float* sb = sm;                 // [UP1][Tn]
    float* sl = sm + UP1 * Tn;      // [Un][Tn]

    const int b   = blockIdx.x;
    const int tid = threadIdx.x;

    // float4 staging (device globals are 256B-aligned; sizes divisible by 4)
    {
        const float4* gb4 = (const float4*)(g_blankT + b * UP1 * Tn);
        const float4* gl4 = (const float4*)(g_labT   + b * Un  * Tn);
        float4* sb4 = (float4*)sb;
        float4* sl4 = (float4*)sl;
        #pragma unroll 4
        for (int i = tid; i < UP1 * Tn / 4; i += 256) sb4[i] = gb4[i];
        #pragma unroll 4
        for (int i = tid; i < Un  * Tn / 4; i += 256) sl4[i] = gl4[i];
    }
    __syncthreads();
    if (tid >= 32) return;

    const int lane  = tid;
    const bool isl0 = (lane == 0);
    const int  rot  = (lane + 31) & 31;
    const int  Tl   = logit_lens[b];
    const int  Ul   = y_lens[b];
    const int  d_hit = Tl - 1 + Ul;

    // per-lane constant smem base offsets (offset + d = live index)
    const int ib0 = 255 * lane - 1;                       // sb for u=lane
    const int il0 = isl0 ? 0 : 255 * lane - 256;          // sl for u=lane   (lane0 dummy)
    const int ib1 = 255 * lane + 8159;                    // sb for u=32+lane
    const int il1 = 255 * lane + 7904;                    // sl for u=32+lane
    const int ib2 = 16319;                                // sb for u=64
    const int il2 = 16064;                                // sl for u=64

    const float NINF = -INFINITY;
    float a0 = isl0 ? 0.f : NINF;   // diag 0: alpha[0,0]=0
    float a1 = NINF;
    float a2 = NINF;

    #pragma unroll 4
    for (int d = 1; d <= (Tn - 1) + Un; ++d) {
        float r0 = __shfl_sync(0xFFFFFFFFu, a0, rot);   // lane l <- a0[l-1]; lane0 <- a0[31]
        float r1 = __shfl_sync(0xFFFFFFFFu, a1, rot);   // lane l <- a1[l-1]; lane0 <- a1[31]
        float p0 = isl0 ? NINF : r0;                    // alpha[t, u0-1] (none at u0=0)
        float p1 = isl0 ? r0   : r1;                    // alpha[t, u1-1] (u=31 bridges at lane0)

        // u = lane
        float n0 = laep2(a0 + sb[ib0 + d], p0 + sl[il0 + d]);
        // u = 32 + lane
        float n1 = laep2(a1 + sb[ib1 + d], p1 + sl[il1 + d]);
        // u = 64 (meaningful on lane 0 only; other lanes compute harmless garbage)
        float n2 = laep2(a2 + sb[ib2 + d], r1 + sl[il2 + d]);

        if (d == d_hit) {   // uniform, taken once
            float nv = (Ul < 32) ? n0 : ((Ul < 64) ? n1 : n2);
            int   hl = (Ul < 32) ? Ul : ((Ul < 64) ? (Ul - 32) : 0);
            if (lane == hl)
                g_loss[b] = -(nv + sb[Ul * Tn + (Tl - 1)]);
        }

        a0 = n0; a1 = n1; a2 = n2;
    }
}

// ---------------------------------------------------------------------------
// Kernel 3: mean over batch
// ---------------------------------------------------------------------------
__global__ void reduce_kernel(float* __restrict__ out)
{
    float v = (threadIdx.x < Bn) ? g_loss[threadIdx.x] : 0.f;
    #pragma unroll
    for (int o = 16; o; o >>= 1)
        v += __shfl_xor_sync(0xFFFFFFFFu, v, o);
    if (threadIdx.x == 0) out[0] = v * (1.0f / Bn);
}

// ---------------------------------------------------------------------------
extern "C" void kernel_launch(void* const* d_in, const int* in_sizes, int n_in,
                              void* d_out, int out_size)
{
    const float* logits     = (const float*)d_in[0];
    const int*   logit_lens = (const int*)  d_in[1];
    const int*   y          = (const int*)  d_in[2];
    const int*   y_lens     = (const int*)  d_in[3];
    (void)in_sizes; (void)n_in; (void)out_size;

    const int blocks = (NROWS + 7) / 8;
    lse_kernel<<<blocks, 256>>>(logits, y);

    const int SMEM_BYTES = (UP1 * Tn + Un * Tn) * (int)sizeof(float);  // 132096
    cudaFuncSetAttribute(alpha_kernel,
                         cudaFuncAttributeMaxDynamicSharedMemorySize, SMEM_BYTES);
    alpha_kernel<<<Bn, 256, SMEM_BYTES>>>(logit_lens, y_lens);

    reduce_kernel<<<1, 32>>>((float*)d_out);
}